// round 15
// baseline (speedup 1.0000x reference)
#include <cuda_runtime.h>
#include <math.h>
#include <stddef.h>
#include <stdint.h>

#define BB   2
#define SS   1024
#define DD   1024
#define HH   16
#define DKK  64
#define LL   4
#define DFFN 4096
#define OUTV 32000
#define MTOK (BB*SS)

// ---------------- scratch (allocation-free: __device__ globals) ----------------
__device__ float g_h [MTOK*DD];
__device__ float g_ht[MTOK*DD];
__device__ float g_q [MTOK*DD];
__device__ float g_k [MTOK*DD];
__device__ float g_v [MTOK*DD];
__device__ float g_attn[MTOK*DD];
__device__ float g_tmp [MTOK*DD];
__device__ float g_ffn[(size_t)MTOK*DFFN];

// transposed + tf32-rounded weights: WT[N][K] (k-major rows)
#define LAYER_WT 12582912ull
#define OFF_WQ 0ull
#define OFF_WK 1048576ull
#define OFF_WV 2097152ull
#define OFF_WO 3145728ull
#define OFF_W1 4194304ull
#define OFF_W2 8388608ull
#define OFF_FC (4ull*LAYER_WT)
#define WT_TOTAL (OFF_FC + 32768000ull)
__device__ float g_wt[WT_TOTAL];

// ---------------- helpers ----------------
__device__ __forceinline__ float tf32r(float x) {
    uint32_t u;
    asm("cvt.rna.tf32.f32 %0, %1;" : "=r"(u) : "f"(x));
    return __uint_as_float(u);
}
__device__ __forceinline__ void mma_tf32(float* c, const uint32_t* a, const uint32_t* b) {
    asm volatile(
        "mma.sync.aligned.m16n8k8.row.col.f32.tf32.tf32.f32 "
        "{%0,%1,%2,%3}, {%4,%5,%6,%7}, {%8,%9}, {%0,%1,%2,%3};"
        : "+f"(c[0]), "+f"(c[1]), "+f"(c[2]), "+f"(c[3])
        : "r"(a[0]), "r"(a[1]), "r"(a[2]), "r"(a[3]), "r"(b[0]), "r"(b[1]));
}
__device__ __forceinline__ void ldsm4(uint32_t* r, uint32_t addr) {
    asm volatile("ldmatrix.sync.aligned.m8n8.x4.shared.b16 {%0,%1,%2,%3}, [%4];"
        : "=r"(r[0]), "=r"(r[1]), "=r"(r[2]), "=r"(r[3]) : "r"(addr));
}
__device__ __forceinline__ void cp16(uint32_t s, const void* g) {
    asm volatile("cp.async.cg.shared.global [%0], [%1], 16;" :: "r"(s), "l"(g));
}
#define CP_COMMIT() asm volatile("cp.async.commit_group;")
#define CP_WAIT1()  asm volatile("cp.async.wait_group 1;")

// ---------------- embedding (writes fp32 h and tf32-rounded ht) -----------------
__global__ void embed_kernel(const int* __restrict__ x, const float* __restrict__ emb,
                             float* __restrict__ h, float* __restrict__ ht) {
    int r = blockIdx.x;
    int tok = x[r];
    const float4* src = (const float4*)(emb + (size_t)tok * DD);
    float4 v = src[threadIdx.x];
    v.x *= 32.0f; v.y *= 32.0f; v.z *= 32.0f; v.w *= 32.0f;   // sqrt(1024)
    ((float4*)(h + (size_t)r * DD))[threadIdx.x] = v;
    float4 t = make_float4(tf32r(v.x), tf32r(v.y), tf32r(v.z), tf32r(v.w));
    ((float4*)(ht + (size_t)r * DD))[threadIdx.x] = t;
}

// ------- weight transpose + tf32 round: W[K][N] -> WT[N][K], 64x64 float4 tiles --
__global__ void __launch_bounds__(256) transpose_round(
    const float* __restrict__ W, float* __restrict__ WT, int K, int N) {
    __shared__ float t[64][65];
    int k0 = blockIdx.x * 64, n0 = blockIdx.y * 64;
    int tid = threadIdx.x;
    #pragma unroll
    for (int p = 0; p < 4; p++) {
        int idx = tid + (p << 8);
        int r = idx >> 4;
        int c4 = (idx & 15) << 2;
        float4 v = *(const float4*)&W[(size_t)(k0 + r) * N + n0 + c4];
        t[r][c4] = v.x; t[r][c4 + 1] = v.y; t[r][c4 + 2] = v.z; t[r][c4 + 3] = v.w;
    }
    __syncthreads();
    #pragma unroll
    for (int p = 0; p < 4; p++) {
        int idx = tid + (p << 8);
        int r = idx >> 4;
        int c4 = (idx & 15) << 2;
        float4 o = make_float4(tf32r(t[c4][r]),     tf32r(t[c4 + 1][r]),
                               tf32r(t[c4 + 2][r]), tf32r(t[c4 + 3][r]));
        *(float4*)&WT[(size_t)(n0 + r) * K + k0 + c4] = o;
    }
}

// =================================================================================
// Dense tf32 GEMM: 128x128 tiles, BK=64 chunks, 3-stage cp.async (209KB smem),
// 8 warps 2x4, warp 64x32, ALL fragments via ldmatrix.x4 (A 4/k-step, B 2/k-step),
// reg double-buffered; ONE barrier pair per 64 K-iterations.
// mode bit0: gelu, bit1: sp mask (+full-tile early exit), bit2: round out to tf32.
// blockIdx.z selects BT/bias/C pointer set (QKV fusion). A stride = K.
// =================================================================================
#define NSTG 3
#define LDT 68
#define TSZ2 (128*LDT)
#define GEMM_SMEM (NSTG*2*TSZ2*4)

__global__ void __launch_bounds__(256) gemm_tc(
    const float* __restrict__ A, int K, int ldc, int mode, const int* __restrict__ sp,
    const float* __restrict__ BT0, const float* __restrict__ bias0, float* __restrict__ C0,
    const float* __restrict__ BT1, const float* __restrict__ bias1, float* __restrict__ C1,
    const float* __restrict__ BT2, const float* __restrict__ bias2, float* __restrict__ C2)
{
    const float* BT = BT0; const float* bias = bias0; float* C = C0;
    if (blockIdx.z == 1) { BT = BT1; bias = bias1; C = C1; }
    else if (blockIdx.z == 2) { BT = BT2; bias = bias2; C = C2; }

    extern __shared__ float sm[];

    int tid = threadIdx.x;
    int lane = tid & 31, warp = tid >> 5;
    int wm = warp >> 2, wn = warp & 3;
    int g = lane >> 2, tg = lane & 3;
    int row0 = blockIdx.x*128, col0 = blockIdx.y*128;

    // full-tile output-mask early exit (LM head only): rows [row0, row0+127]
    // all within one batch; if max si < start_pos, entire tile is zeroed.
    if ((mode & 2) && ((row0 & 1023) + 127) < sp[row0 >> 10]) {
        #pragma unroll
        for (int m = 0; m < 4; m++) {
            int r0 = row0 + wm*64 + m*16 + g;
            #pragma unroll
            for (int n = 0; n < 4; n++) {
                int c = col0 + wn*32 + n*8 + tg*2;
                *(float2*)&C[(size_t)r0 * ldc + c]       = make_float2(0.0f, 0.0f);
                *(float2*)&C[(size_t)(r0 + 8) * ldc + c] = make_float2(0.0f, 0.0f);
            }
        }
        return;
    }

    const float* Abase = A  + (size_t)row0 * K;
    const float* Bbase = BT + (size_t)col0 * K;

    uint32_t sA = (uint32_t)__cvta_generic_to_shared(sm);
    int lrow = lane & 15, lcol = (lane >> 4) << 2;

    int nch = K >> 6;    // 64-deep chunks

// stage s: A tile at s*2*TSZ2, B tile at s*2*TSZ2 + TSZ2; rows 128 x 64k, stride 68
#define ISSUE_STAGE(s_, k0_) do {                                              \
    uint32_t dA_ = sA + (uint32_t)((s_)*2*TSZ2) * 4;                           \
    uint32_t dB_ = dA_ + (uint32_t)TSZ2 * 4;                                   \
    _Pragma("unroll")                                                          \
    for (int p_ = 0; p_ < 8; p_++) {                                           \
        int i_ = tid + (p_ << 8);                                              \
        int r_ = i_ >> 4, c_ = (i_ & 15) << 2;                                 \
        cp16(dA_ + (uint32_t)(r_*LDT + c_)*4, Abase + (size_t)r_*K + (k0_) + c_); \
        cp16(dB_ + (uint32_t)(r_*LDT + c_)*4, Bbase + (size_t)r_*K + (k0_) + c_); \
    }                                                                          \
} while (0)

    // prologue: stages 0,1
    ISSUE_STAGE(0, 0);  CP_COMMIT();
    ISSUE_STAGE(1, 64); CP_COMMIT();
    CP_WAIT1();
    __syncthreads();

    float acc[4][4][4] = {};
    uint32_t afr[2][4][4], bfr[2][2][4];

#define LOADF(buf_, s_, kc_) do {                                              \
    uint32_t asw_ = sA + (uint32_t)((s_)*2*TSZ2) * 4;                          \
    uint32_t bsw_ = asw_ + (uint32_t)TSZ2 * 4;                                 \
    _Pragma("unroll")                                                          \
    for (int m_ = 0; m_ < 4; m_++) {                                           \
        uint32_t ad_ = asw_ + (uint32_t)((wm*64 + m_*16 + lrow)*LDT + (kc_) + lcol)*4; \
        ldsm4(afr[buf_][m_], ad_);                                             \
    }                                                                          \
    _Pragma("unroll")                                                          \
    for (int q_ = 0; q_ < 2; q_++) {                                           \
        uint32_t bd_ = bsw_ + (uint32_t)((wn*32 + q_*16 + lrow)*LDT + (kc_) + lcol)*4; \
        ldsm4(bfr[buf_][q_], bd_);                                             \
    }                                                                          \
} while (0)

#define MMAALL(buf_) do {                                                      \
    _Pragma("unroll")                                                          \
    for (int m_ = 0; m_ < 4; m_++)                                             \
        _Pragma("unroll")                                                      \
        for (int n_ = 0; n_ < 4; n_++) {                                       \
            uint32_t b_[2];                                                    \
            b_[0] = bfr[buf_][n_ >> 1][n_ & 1];                                \
            b_[1] = bfr[buf_][n_ >> 1][2 + (n_ & 1)];                          \
            mma_tf32(acc[m_][n_], afr[buf_][m_], b_);                          \
        }                                                                      \
} while (0)

    LOADF(0, 0, 0);

    for (int ch = 0; ch < nch; ch++) {
        int st = ch % NSTG;
        LOADF(1, st, 8);   MMAALL(0);
        LOADF(0, st, 16);  MMAALL(1);
        LOADF(1, st, 24);  MMAALL(0);
        LOADF(0, st, 32);  MMAALL(1);
        LOADF(1, st, 40);  MMAALL(0);
        LOADF(0, st, 48);  MMAALL(1);
        LOADF(1, st, 56);  MMAALL(0);
        if (ch + 2 < nch) {
            ISSUE_STAGE((ch + 2) % NSTG, (ch + 2) << 6);
        }
        CP_COMMIT();
        CP_WAIT1();
        __syncthreads();
        if (ch + 1 < nch) LOADF(0, (ch + 1) % NSTG, 0);
        MMAALL(1);
    }

    // epilogue
    #pragma unroll
    for (int m = 0; m < 4; m++) {
        int r0 = row0 + wm*64 + m*16 + g;
        #pragma unroll
        for (int n = 0; n < 4; n++) {
            int c = col0 + wn*32 + n*8 + tg*2;
            float b0f = bias ? bias[c] : 0.0f;
            float b1f = bias ? bias[c + 1] : 0.0f;
            float v[4] = { acc[m][n][0] + b0f, acc[m][n][1] + b1f,
                           acc[m][n][2] + b0f, acc[m][n][3] + b1f };
            if (mode & 1) {
                #pragma unroll
                for (int i = 0; i < 4; i++)
                    v[i] = 0.5f * v[i] * (1.0f + erff(v[i] * 0.70710678118654752f));
            }
            if (mode & 2) {
                int r1 = r0 + 8;
                if ((r0 & 1023) < sp[r0 >> 10]) { v[0] = 0.0f; v[1] = 0.0f; }
                if ((r1 & 1023) < sp[r1 >> 10]) { v[2] = 0.0f; v[3] = 0.0f; }
            }
            if (mode & 4) {
                #pragma unroll
                for (int i = 0; i < 4; i++) v[i] = tf32r(v[i]);
            }
            *(float2*)&C[(size_t)r0 * ldc + c]       = make_float2(v[0], v[1]);
            *(float2*)&C[(size_t)(r0 + 8) * ldc + c] = make_float2(v[2], v[3]);
        }
    }
}

// =================================================================================
// Flash attention, ldsm edition (round-14 version, unchanged)
// =================================================================================
#define KS_LD 68
#define VS_LD 72
#define PS_LD 132
#define KS_SZ (128*KS_LD)
#define VS_SZ (128*VS_LD)
#define FA_SMEM ((2*KS_SZ + 2*VS_SZ + 128*PS_LD)*4)

__global__ void __launch_bounds__(256,1) flash_attn(
    const float* __restrict__ Q, const float* __restrict__ Kg,
    const float* __restrict__ Vg, float* __restrict__ O,
    const int* __restrict__ sp)
{
    int z = blockIdx.z, bi = z >> 4, hi = z & 15;
    int q0 = blockIdx.x * 128;
    const float* Qb = Q  + (size_t)bi*SS*DD + hi*DKK;
    const float* Kb = Kg + (size_t)bi*SS*DD + hi*DKK;
    const float* Vb = Vg + (size_t)bi*SS*DD + hi*DKK;
    float* Ob = O + (size_t)bi*SS*DD + hi*DKK;

    extern __shared__ float sm[];
    float* Vs = sm + 2*KS_SZ;
    float* Ps = sm + 2*KS_SZ + 2*VS_SZ;
    uint32_t sBase = (uint32_t)__cvta_generic_to_shared(sm);
    uint32_t sVs = sBase + (uint32_t)(2*KS_SZ)*4;
    uint32_t sPs = sVs + (uint32_t)(2*VS_SZ)*4;

    int tid = threadIdx.x;
    int lane = tid & 31, warp = tid >> 5;
    int g = lane >> 2, tg = lane & 3;
    int lrow = lane & 15, lcol = (lane >> 4) << 2;
    int wq = warp * 16;
    int spv = sp[bi];
    float slope = exp2f(-0.5f * (float)(hi + 1));

    #pragma unroll
    for (int p = 0; p < 8; p++) {
        int i = tid + (p << 8);
        int r = i >> 4, c = (i & 15) << 2;
        *(float4*)&Ps[r*PS_LD + c] = *(const float4*)(Qb + (size_t)(q0 + r)*DD + c);
    }
    __syncthreads();
    uint32_t aq[8][4];
    #pragma unroll
    for (int kf = 0; kf < 8; kf++) {
        uint32_t ad = sPs + (uint32_t)((wq + lrow)*PS_LD + kf*8 + lcol)*4;
        ldsm4(aq[kf], ad);
    }
    __syncthreads();

    int nt = (q0 >= 256) ? (q0 >> 7) + 1 : 8;

    {
        #pragma unroll
        for (int p = 0; p < 8; p++) {
            int i = tid + (p << 8);
            int r = i >> 4, c = (i & 15) << 2;
            cp16(sBase + (uint32_t)(r*KS_LD + c)*4, Kb + (size_t)r*DD + c);
            cp16(sVs   + (uint32_t)(r*VS_LD + c)*4, Vb + (size_t)r*DD + c);
        }
        CP_COMMIT();
    }

    float m_i[2] = {-1e30f, -1e30f};
    float l_i[2] = {0.0f, 0.0f};
    float acc_o[8][4] = {};
    float* Pw = Ps + wq*PS_LD;
    uint32_t sPw = sPs + (uint32_t)(wq*PS_LD)*4;

    for (int t = 0; t < nt; t++) {
        __syncthreads();
        if (t + 1 < nt) {
            int st = (t + 1) & 1;
            const float* Kt = Kb + (size_t)((t+1) << 7)*DD;
            const float* Vt = Vb + (size_t)((t+1) << 7)*DD;
            #pragma unroll
            for (int p = 0; p < 8; p++) {
                int i = tid + (p << 8);
                int r = i >> 4, c = (i & 15) << 2;
                cp16(sBase + (uint32_t)(st*KS_SZ + r*KS_LD + c)*4, Kt + (size_t)r*DD + c);
                cp16(sVs   + (uint32_t)(st*VS_SZ + r*VS_LD + c)*4, Vt + (size_t)r*DD + c);
            }
        }
        CP_COMMIT();
        CP_WAIT1();
        __syncthreads();

        uint32_t ksb = sBase + (uint32_t)((t & 1)*KS_SZ)*4;
        const float* vs = Vs + (t & 1)*VS_SZ;

        float acc_s[16][4] = {};
        #pragma unroll
        for (int kf = 0; kf < 8; kf++) {
            int kc = kf << 3;
            #pragma unroll
            for (int nf2 = 0; nf2 < 8; nf2++) {
                uint32_t kb[4];
                ldsm4(kb, ksb + (uint32_t)((nf2*16 + lrow)*KS_LD + kc + lcol)*4);
                { uint32_t b_[2] = { kb[0], kb[2] }; mma_tf32(acc_s[2*nf2],     aq[kf], b_); }
                { uint32_t b_[2] = { kb[1], kb[3] }; mma_tf32(acc_s[2*nf2 + 1], aq[kf], b_); }
            }
        }

        int c0 = t << 7;
        int qr0 = q0 + wq + g, qr1 = qr0 + 8;
        float tm0 = -1e30f, tm1 = -1e30f;
        #pragma unroll
        for (int nf = 0; nf < 16; nf++) {
            int c = c0 + nf*8 + tg*2;
            #pragma unroll
            for (int j = 0; j < 2; j++) {
                int cc = c + j;
                float s0 = acc_s[nf][j]   * 0.125f + slope * (float)(cc - qr0);
                float s1 = acc_s[nf][j+2] * 0.125f + slope * (float)(cc - qr1);
                bool ok0 = (qr0 >= cc) || (qr0 < spv) || (cc < spv);
                bool ok1 = (qr1 >= cc) || (qr1 < spv) || (cc < spv);
                acc_s[nf][j]   = ok0 ? s0 : -1e9f;
                acc_s[nf][j+2] = ok1 ? s1 : -1e9f;
                tm0 = fmaxf(tm0, acc_s[nf][j]);
                tm1 = fmaxf(tm1, acc_s[nf][j+2]);
            }
        }
        tm0 = fmaxf(tm0, __shfl_xor_sync(0xffffffffu, tm0, 1));
        tm0 = fmaxf(tm0, __shfl_xor_sync(0xffffffffu, tm0, 2));
        tm1 = fmaxf(tm1, __shfl_xor_sync(0xffffffffu, tm1, 1));
        tm1 = fmaxf(tm1, __shfl_xor_sync(0xffffffffu, tm1, 2));

        float mn0 = fmaxf(m_i[0], tm0), mn1 = fmaxf(m_i[1], tm1);
        float al0 = expf(m_i[0] - mn0),  al1 = expf(m_i[1] - mn1);
        m_i[0] = mn0; m_i[1] = mn1;

        float rs0 = 0.0f, rs1 = 0.0f;
        #pragma unroll
        for (int nf = 0; nf < 16; nf++) {
            float p0 = expf(acc_s[nf][0] - mn0);
            float p1 = expf(acc_s[nf][1] - mn0);
            float p2 = expf(acc_s[nf][2] - mn1);
            float p3 = expf(acc_s[nf][3] - mn1);
            rs0 += p0 + p1; rs1 += p2 + p3;
            int col = nf*8 + tg*2;
            *(float2*)&Pw[g*PS_LD + col]     = make_float2(tf32r(p0), tf32r(p1));
            *(float2*)&Pw[(g+8)*PS_LD + col] = make_float2(tf32r(p2), tf32r(p3));
        }
        rs0 += __shfl_xor_sync(0xffffffffu, rs0, 1);
        rs0 += __shfl_xor_sync(0xffffffffu, rs0, 2);
        rs1 += __shfl_xor_sync(0xffffffffu, rs1, 1);
        rs1 += __shfl_xor_sync(0xffffffffu, rs1, 2);
        l_i[0] = l_i[0]*al0 + rs0;
        l_i[1] = l_i[1]*al1 + rs1;

        #pragma unroll
        for (int nf = 0; nf < 8; nf++) {
            acc_o[nf][0] *= al0; acc_o[nf][1] *= al0;
            acc_o[nf][2] *= al1; acc_o[nf][3] *= al1;
        }
        __syncwarp();

        #pragma unroll
        for (int kf = 0; kf < 16; kf++) {
            int kc = kf << 3;
            uint32_t af[4];
            ldsm4(af, sPw + (uint32_t)(lrow*PS_LD + kc + lcol)*4);
            #pragma unroll
            for (int nf = 0; nf < 8; nf++) {
                uint32_t bf[2];
                const float* q2 = vs + (kc + tg)*VS_LD + nf*8 + g;
                bf[0] = __float_as_uint(q2[0]);
                bf[1] = __float_as_uint(q2[4*VS_LD]);
                mma_tf32(acc_o[nf], af, bf);
            }
        }
        __syncwarp();
    }

    float inv0 = 1.0f / l_i[0], inv1 = 1.0f / l_i[1];
    int qr0 = q0 + wq + g;
    #pragma unroll
    for (int nf = 0; nf < 8; nf++) {
        int c = nf*8 + tg*2;
        *(float2*)&Ob[(size_t)qr0*DD + c] =
            make_float2(tf32r(acc_o[nf][0]*inv0), tf32r(acc_o[nf][1]*inv0));
        *(float2*)&Ob[(size_t)(qr0+8)*DD + c] =
            make_float2(tf32r(acc_o[nf][2]*inv1), tf32r(acc_o[nf][3]*inv1));
    }
}

// ---------------- residual add + layernorm; writes fp32 out + tf32 out_t --------
__global__ void __launch_bounds__(256) add_ln(
    const float* __restrict__ X, const float* __restrict__ Rs,
    const float* __restrict__ g, const float* __restrict__ bta,
    float* __restrict__ out, float* __restrict__ out_t)
{
    int r = blockIdx.x, tid = threadIdx.x;
    const float4* x4 = (const float4*)(X + (size_t)r * DD);
    const float4* r4 = (const float4*)(Rs + (size_t)r * DD);
    float4 xv = x4[tid], rv = r4[tid];
    float v0 = xv.x + rv.x, v1 = xv.y + rv.y, v2 = xv.z + rv.z, v3 = xv.w + rv.w;
    float s1 = v0 + v1 + v2 + v3;
    float s2 = v0*v0 + v1*v1 + v2*v2 + v3*v3;

    __shared__ float rA[256], rB[256];
    rA[tid] = s1; rB[tid] = s2; __syncthreads();
    for (int s = 128; s > 0; s >>= 1) {
        if (tid < s) { rA[tid] += rA[tid + s]; rB[tid] += rB[tid + s]; }
        __syncthreads();
    }
    float mu = rA[0] * (1.0f / 1024.0f);
    float var = rB[0] * (1.0f / 1024.0f) - mu * mu;
    float rstd = rsqrtf(var + 1e-5f);

    const float4 gv = ((const float4*)g)[tid];
    const float4 bv = ((const float4*)bta)[tid];
    float4 o;
    o.x = (v0 - mu) * rstd * gv.x + bv.x;
    o.y = (v1 - mu) * rstd * gv.y + bv.y;
    o.z = (v2 - mu) * rstd * gv.z + bv.z;
    o.w = (v3 - mu) * rstd * gv.w + bv.w;
    ((float4*)(out + (size_t)r * DD))[tid] = o;
    float4 t = make_float4(tf32r(o.x), tf32r(o.y), tf32r(o.z), tf32r(o.w));
    ((float4*)(out_t + (size_t)r * DD))[tid] = t;
}

// ---------------- launch ----------------
extern "C" void kernel_launch(void* const* d_in, const int* in_sizes, int n_in,
                              void* d_out, int out_size) {
    (void)in_sizes; (void)n_in; (void)out_size;
    const int*   x    = (const int*)  d_in[0];
    const int*   sp   = (const int*)  d_in[1];
    const float* emb  = (const float*)d_in[2];
    const float* Wq   = (const float*)d_in[3];
    const float* bq   = (const float*)d_in[4];
    const float* Wk   = (const float*)d_in[5];
    const float* bk   = (const float*)d_in[6];
    const float* Wv   = (const float*)d_in[7];
    const float* bv   = (const float*)d_in[8];
    const float* Wo   = (const float*)d_in[9];
    const float* bo   = (const float*)d_in[10];
    const float* ln1g = (const float*)d_in[11];
    const float* ln1b = (const float*)d_in[12];
    const float* W1   = (const float*)d_in[13];
    const float* b1   = (const float*)d_in[14];
    const float* W2   = (const float*)d_in[15];
    const float* b2   = (const float*)d_in[16];
    const float* ln2g = (const float*)d_in[17];
    const float* ln2b = (const float*)d_in[18];
    const float* fcw  = (const float*)d_in[19];
    const float* fcb  = (const float*)d_in[20];
    float* out = (float*)d_out;

    float *h, *ht, *q, *k, *v, *attn, *tmp, *ffn, *wt;
    cudaGetSymbolAddress((void**)&h,    g_h);
    cudaGetSymbolAddress((void**)&ht,   g_ht);
    cudaGetSymbolAddress((void**)&q,    g_q);
    cudaGetSymbolAddress((void**)&k,    g_k);
    cudaGetSymbolAddress((void**)&v,    g_v);
    cudaGetSymbolAddress((void**)&attn, g_attn);
    cudaGetSymbolAddress((void**)&tmp,  g_tmp);
    cudaGetSymbolAddress((void**)&ffn,  g_ffn);
    cudaGetSymbolAddress((void**)&wt,   g_wt);

    static int inited = 0;
    static cudaStream_t side;
    static cudaEvent_t evFork, evQKV[LL], evWOF[LL], evFC;
    if (!inited) {
        cudaFuncSetAttribute(gemm_tc,    cudaFuncAttributeMaxDynamicSharedMemorySize, GEMM_SMEM);
        cudaFuncSetAttribute(flash_attn, cudaFuncAttributeMaxDynamicSharedMemorySize, FA_SMEM);
        cudaStreamCreateWithFlags(&side, cudaStreamNonBlocking);
        cudaEventCreateWithFlags(&evFork, cudaEventDisableTiming);
        for (int l = 0; l < LL; l++) {
            cudaEventCreateWithFlags(&evQKV[l], cudaEventDisableTiming);
            cudaEventCreateWithFlags(&evWOF[l], cudaEventDisableTiming);
        }
        cudaEventCreateWithFlags(&evFC, cudaEventDisableTiming);
        inited = 1;
    }

    const float* NUL = 0;
    float* NULF = 0;

    // ---- side stream: weight transpose + tf32 round prepass, fine-grained events ----
    cudaEventRecord(evFork, 0);
    cudaStreamWaitEvent(side, evFork, 0);
    for (int l = 0; l < LL; l++) {
        size_t lb = (size_t)l * LAYER_WT;
        transpose_round<<<dim3(16, 16), 256, 0, side>>>(Wq + (size_t)l*DD*DD,  wt + lb + OFF_WQ, DD, DD);
        transpose_round<<<dim3(16, 16), 256, 0, side>>>(Wk + (size_t)l*DD*DD,  wt + lb + OFF_WK, DD, DD);
        transpose_round<<<dim3(16, 16), 256, 0, side>>>(Wv + (size_t)l*DD*DD,  wt + lb + OFF_WV, DD, DD);
        cudaEventRecord(evQKV[l], side);
        transpose_round<<<dim3(16, 16), 256, 0, side>>>(Wo + (size_t)l*DD*DD,  wt + lb + OFF_WO, DD, DD);
        transpose_round<<<dim3(16, 64), 256, 0, side>>>(W1 + (size_t)l*DD*DFFN, wt + lb + OFF_W1, DD, DFFN);
        transpose_round<<<dim3(64, 16), 256, 0, side>>>(W2 + (size_t)l*DFFN*DD, wt + lb + OFF_W2, DFFN, DD);
        cudaEventRecord(evWOF[l], side);
    }
    transpose_round<<<dim3(16, 500), 256, 0, side>>>(fcw, wt + OFF_FC, DD, OUTV);
    cudaEventRecord(evFC, side);

    // ---- main stream ----
    embed_kernel<<<MTOK, 256>>>(x, emb, h, ht);

    for (int l = 0; l < LL; l++) {
        size_t lb = (size_t)l * LAYER_WT;

        cudaStreamWaitEvent(0, evQKV[l], 0);
        gemm_tc<<<dim3(MTOK/128, DD/128, 3), 256, GEMM_SMEM>>>(
            ht, DD, DD, 4, (const int*)0,
            wt + lb + OFF_WQ, bq + (size_t)l*DD, q,
            wt + lb + OFF_WK, bk + (size_t)l*DD, k,
            wt + lb + OFF_WV, bv + (size_t)l*DD, v);

        flash_attn<<<dim3(SS/128, 1, BB*HH), 256, FA_SMEM>>>(q, k, v, attn, sp);

        cudaStreamWaitEvent(0, evWOF[l], 0);
        gemm_tc<<<dim3(MTOK/128, DD/128, 1), 256, GEMM_SMEM>>>(
            attn, DD, DD, 0, (const int*)0,
            wt + lb + OFF_WO, bo + (size_t)l*DD, tmp,
            NUL, NUL, NULF, NUL, NUL, NULF);
        add_ln<<<MTOK, 256>>>(h, tmp, ln1g + (size_t)l*DD, ln1b + (size_t)l*DD, h, ht);

        gemm_tc<<<dim3(MTOK/128, DFFN/128, 1), 256, GEMM_SMEM>>>(
            ht, DD, DFFN, 1 | 4, (const int*)0,
            wt + lb + OFF_W1, b1 + (size_t)l*DFFN, ffn,
            NUL, NUL, NULF, NUL, NUL, NULF);
        gemm_tc<<<dim3(MTOK/128, DD/128, 1), 256, GEMM_SMEM>>>(
            ffn, DFFN, DD, 0, (const int*)0,
            wt + lb + OFF_W2, b2 + (size_t)l*DD, tmp,
            NUL, NUL, NULF, NUL, NUL, NULF);
        add_ln<<<MTOK, 256>>>(h, tmp, ln2g + (size_t)l*DD, ln2b + (size_t)l*DD, h, ht);
    }

    cudaStreamWaitEvent(0, evFC, 0);
    gemm_tc<<<dim3(MTOK/128, OUTV/128, 1), 256, GEMM_SMEM>>>(
        ht, DD, OUTV, 2, sp,
        wt + OFF_FC, fcb, out,
        NUL, NUL, NULF, NUL, NUL, NULF);
}

// round 16
// speedup vs baseline: 1.0602x; 1.0602x over previous
#include <cuda_runtime.h>
#include <math.h>
#include <stddef.h>
#include <stdint.h>

#define BB   2
#define SS   1024
#define DD   1024
#define HH   16
#define DKK  64
#define LL   4
#define DFFN 4096
#define OUTV 32000
#define MTOK (BB*SS)

// ---------------- scratch (allocation-free: __device__ globals) ----------------
__device__ float g_h [MTOK*DD];
__device__ float g_ht[MTOK*DD];
__device__ float g_q [MTOK*DD];
__device__ float g_k [MTOK*DD];
__device__ float g_v [MTOK*DD];
__device__ float g_attn[MTOK*DD];
__device__ float g_tmp [MTOK*DD];
__device__ float g_ffn[(size_t)MTOK*DFFN];

// transposed + tf32-rounded weights: WT[N][K] (k-major rows)
#define LAYER_WT 12582912ull
#define OFF_WQ 0ull
#define OFF_WK 1048576ull
#define OFF_WV 2097152ull
#define OFF_WO 3145728ull
#define OFF_W1 4194304ull
#define OFF_W2 8388608ull
#define OFF_FC (4ull*LAYER_WT)
#define WT_TOTAL (OFF_FC + 32768000ull)
__device__ float g_wt[WT_TOTAL];

// ---------------- helpers ----------------
__device__ __forceinline__ float tf32r(float x) {
    uint32_t u;
    asm("cvt.rna.tf32.f32 %0, %1;" : "=r"(u) : "f"(x));
    return __uint_as_float(u);
}
__device__ __forceinline__ void mma_tf32(float* c, const uint32_t* a, const uint32_t* b) {
    asm volatile(
        "mma.sync.aligned.m16n8k8.row.col.f32.tf32.tf32.f32 "
        "{%0,%1,%2,%3}, {%4,%5,%6,%7}, {%8,%9}, {%0,%1,%2,%3};"
        : "+f"(c[0]), "+f"(c[1]), "+f"(c[2]), "+f"(c[3])
        : "r"(a[0]), "r"(a[1]), "r"(a[2]), "r"(a[3]), "r"(b[0]), "r"(b[1]));
}
__device__ __forceinline__ void ldsm4(uint32_t* r, uint32_t addr) {
    asm volatile("ldmatrix.sync.aligned.m8n8.x4.shared.b16 {%0,%1,%2,%3}, [%4];"
        : "=r"(r[0]), "=r"(r[1]), "=r"(r[2]), "=r"(r[3]) : "r"(addr));
}
__device__ __forceinline__ void cp16(uint32_t s, const void* g) {
    asm volatile("cp.async.cg.shared.global [%0], [%1], 16;" :: "r"(s), "l"(g));
}
#define CP_COMMIT() asm volatile("cp.async.commit_group;")
#define CP_WAIT2()  asm volatile("cp.async.wait_group 2;")
#define CP_WAIT1()  asm volatile("cp.async.wait_group 1;")

// ---------------- embedding (writes fp32 h and tf32-rounded ht) -----------------
__global__ void embed_kernel(const int* __restrict__ x, const float* __restrict__ emb,
                             float* __restrict__ h, float* __restrict__ ht) {
    int r = blockIdx.x;
    int tok = x[r];
    const float4* src = (const float4*)(emb + (size_t)tok * DD);
    float4 v = src[threadIdx.x];
    v.x *= 32.0f; v.y *= 32.0f; v.z *= 32.0f; v.w *= 32.0f;   // sqrt(1024)
    ((float4*)(h + (size_t)r * DD))[threadIdx.x] = v;
    float4 t = make_float4(tf32r(v.x), tf32r(v.y), tf32r(v.z), tf32r(v.w));
    ((float4*)(ht + (size_t)r * DD))[threadIdx.x] = t;
}

// ------- weight transpose + tf32 round: W[K][N] -> WT[N][K], 64x64 float4 tiles --
__global__ void __launch_bounds__(256) transpose_round(
    const float* __restrict__ W, float* __restrict__ WT, int K, int N) {
    __shared__ float t[64][65];
    int k0 = blockIdx.x * 64, n0 = blockIdx.y * 64;
    int tid = threadIdx.x;
    #pragma unroll
    for (int p = 0; p < 4; p++) {
        int idx = tid + (p << 8);
        int r = idx >> 4;
        int c4 = (idx & 15) << 2;
        float4 v = *(const float4*)&W[(size_t)(k0 + r) * N + n0 + c4];
        t[r][c4] = v.x; t[r][c4 + 1] = v.y; t[r][c4 + 2] = v.z; t[r][c4 + 3] = v.w;
    }
    __syncthreads();
    #pragma unroll
    for (int p = 0; p < 4; p++) {
        int idx = tid + (p << 8);
        int r = idx >> 4;
        int c4 = (idx & 15) << 2;
        float4 o = make_float4(tf32r(t[c4][r]),     tf32r(t[c4 + 1][r]),
                               tf32r(t[c4 + 2][r]), tf32r(t[c4 + 3][r]));
        *(float4*)&WT[(size_t)(n0 + r) * K + k0 + c4] = o;
    }
}

// =================================================================================
// Dense tf32 GEMM (round-14 proven config): 128x128x32 tiles, 4-stage cp.async,
// 8 warps 2x4, warp 64x32, ALL fragments via ldmatrix.x4, reg double-buffered.
// mode bit0: gelu, bit1: sp mask (+full-tile early exit), bit2: round out to tf32.
// blockIdx.z selects BT/bias/C pointer set (QKV fusion). A stride = K.
// =================================================================================
#define NSTG 4
#define TSZ (128*36)
#define GEMM_SMEM (NSTG*2*TSZ*4)

__global__ void __launch_bounds__(256) gemm_tc(
    const float* __restrict__ A, int K, int ldc, int mode, const int* __restrict__ sp,
    const float* __restrict__ BT0, const float* __restrict__ bias0, float* __restrict__ C0,
    const float* __restrict__ BT1, const float* __restrict__ bias1, float* __restrict__ C1,
    const float* __restrict__ BT2, const float* __restrict__ bias2, float* __restrict__ C2)
{
    const float* BT = BT0; const float* bias = bias0; float* C = C0;
    if (blockIdx.z == 1) { BT = BT1; bias = bias1; C = C1; }
    else if (blockIdx.z == 2) { BT = BT2; bias = bias2; C = C2; }

    extern __shared__ float sm[];

    int tid = threadIdx.x;
    int lane = tid & 31, warp = tid >> 5;
    int wm = warp >> 2, wn = warp & 3;
    int g = lane >> 2, tg = lane & 3;
    int row0 = blockIdx.x*128, col0 = blockIdx.y*128;

    // full-tile output-mask early exit (LM head only)
    if ((mode & 2) && ((row0 & 1023) + 127) < sp[row0 >> 10]) {
        #pragma unroll
        for (int m = 0; m < 4; m++) {
            int r0 = row0 + wm*64 + m*16 + g;
            #pragma unroll
            for (int n = 0; n < 4; n++) {
                int c = col0 + wn*32 + n*8 + tg*2;
                *(float2*)&C[(size_t)r0 * ldc + c]       = make_float2(0.0f, 0.0f);
                *(float2*)&C[(size_t)(r0 + 8) * ldc + c] = make_float2(0.0f, 0.0f);
            }
        }
        return;
    }

    const float* Abase = A  + (size_t)row0 * K;
    const float* Bbase = BT + (size_t)col0 * K;

    int a_r = tid >> 3, a_c = (tid & 7) << 2;
    uint32_t sA = (uint32_t)__cvta_generic_to_shared(sm);

    int lrow = lane & 15, lcol = (lane >> 4) << 2;

    int nch = K >> 5;

#define ISSUE_STAGE(s_, k0_) do {                                              \
    uint32_t dA_ = sA + (uint32_t)((s_)*2*TSZ) * 4;                            \
    uint32_t dB_ = dA_ + (uint32_t)TSZ * 4;                                    \
    _Pragma("unroll")                                                          \
    for (int p_ = 0; p_ < 4; p_++) {                                           \
        int r_ = a_r + 32*p_;                                                  \
        cp16(dA_ + (uint32_t)(r_*36 + a_c)*4, Abase + (size_t)r_*K + (k0_) + a_c); \
        cp16(dB_ + (uint32_t)(r_*36 + a_c)*4, Bbase + (size_t)r_*K + (k0_) + a_c); \
    }                                                                          \
} while (0)

    #pragma unroll
    for (int s = 0; s < 3; s++) {
        ISSUE_STAGE(s, s << 5);
        CP_COMMIT();
    }
    CP_WAIT2();
    __syncthreads();

    float acc[4][4][4] = {};
    uint32_t afr[2][4][4], bfr[2][2][4];

#define LOADF(buf_, s_, kc_) do {                                              \
    uint32_t asw_ = sA + (uint32_t)((s_)*2*TSZ) * 4;                           \
    uint32_t bsw_ = asw_ + (uint32_t)TSZ * 4;                                  \
    _Pragma("unroll")                                                          \
    for (int m_ = 0; m_ < 4; m_++) {                                           \
        uint32_t ad_ = asw_ + (uint32_t)((wm*64 + m_*16 + lrow)*36 + (kc_) + lcol)*4; \
        ldsm4(afr[buf_][m_], ad_);                                             \
    }                                                                          \
    _Pragma("unroll")                                                          \
    for (int q_ = 0; q_ < 2; q_++) {                                           \
        uint32_t bd_ = bsw_ + (uint32_t)((wn*32 + q_*16 + lrow)*36 + (kc_) + lcol)*4; \
        ldsm4(bfr[buf_][q_], bd_);                                             \
    }                                                                          \
} while (0)

#define MMAALL(buf_) do {                                                      \
    _Pragma("unroll")                                                          \
    for (int m_ = 0; m_ < 4; m_++)                                             \
        _Pragma("unroll")                                                      \
        for (int n_ = 0; n_ < 4; n_++) {                                       \
            uint32_t b_[2];                                                    \
            b_[0] = bfr[buf_][n_ >> 1][n_ & 1];                                \
            b_[1] = bfr[buf_][n_ >> 1][2 + (n_ & 1)];                          \
            mma_tf32(acc[m_][n_], afr[buf_][m_], b_);                          \
        }                                                                      \
} while (0)

    LOADF(0, 0, 0);

    for (int ch = 0; ch < nch; ch++) {
        int st = ch & (NSTG - 1);
        LOADF(1, st, 8);   MMAALL(0);
        LOADF(0, st, 16);  MMAALL(1);
        LOADF(1, st, 24);  MMAALL(0);
        if (ch + 3 < nch) {
            ISSUE_STAGE((ch + 3) & (NSTG - 1), (ch + 3) << 5);
        }
        CP_COMMIT();
        CP_WAIT2();
        __syncthreads();
        if (ch + 1 < nch) LOADF(0, (ch + 1) & (NSTG - 1), 0);
        MMAALL(1);
    }

    #pragma unroll
    for (int m = 0; m < 4; m++) {
        int r0 = row0 + wm*64 + m*16 + g;
        #pragma unroll
        for (int n = 0; n < 4; n++) {
            int c = col0 + wn*32 + n*8 + tg*2;
            float b0f = bias ? bias[c] : 0.0f;
            float b1f = bias ? bias[c + 1] : 0.0f;
            float v[4] = { acc[m][n][0] + b0f, acc[m][n][1] + b1f,
                           acc[m][n][2] + b0f, acc[m][n][3] + b1f };
            if (mode & 1) {
                #pragma unroll
                for (int i = 0; i < 4; i++)
                    v[i] = 0.5f * v[i] * (1.0f + erff(v[i] * 0.70710678118654752f));
            }
            if (mode & 2) {
                int r1 = r0 + 8;
                if ((r0 & 1023) < sp[r0 >> 10]) { v[0] = 0.0f; v[1] = 0.0f; }
                if ((r1 & 1023) < sp[r1 >> 10]) { v[2] = 0.0f; v[3] = 0.0f; }
            }
            if (mode & 4) {
                #pragma unroll
                for (int i = 0; i < 4; i++) v[i] = tf32r(v[i]);
            }
            *(float2*)&C[(size_t)r0 * ldc + c]       = make_float2(v[0], v[1]);
            *(float2*)&C[(size_t)(r0 + 8) * ldc + c] = make_float2(v[2], v[3]);
        }
    }
}

// =================================================================================
// Flash attention, ldsm edition (round-14 version, unchanged)
// =================================================================================
#define KS_LD 68
#define VS_LD 72
#define PS_LD 132
#define KS_SZ (128*KS_LD)
#define VS_SZ (128*VS_LD)
#define FA_SMEM ((2*KS_SZ + 2*VS_SZ + 128*PS_LD)*4)

__global__ void __launch_bounds__(256,1) flash_attn(
    const float* __restrict__ Q, const float* __restrict__ Kg,
    const float* __restrict__ Vg, float* __restrict__ O,
    const int* __restrict__ sp)
{
    int z = blockIdx.z, bi = z >> 4, hi = z & 15;
    int q0 = blockIdx.x * 128;
    const float* Qb = Q  + (size_t)bi*SS*DD + hi*DKK;
    const float* Kb = Kg + (size_t)bi*SS*DD + hi*DKK;
    const float* Vb = Vg + (size_t)bi*SS*DD + hi*DKK;
    float* Ob = O + (size_t)bi*SS*DD + hi*DKK;

    extern __shared__ float sm[];
    float* Vs = sm + 2*KS_SZ;
    float* Ps = sm + 2*KS_SZ + 2*VS_SZ;
    uint32_t sBase = (uint32_t)__cvta_generic_to_shared(sm);
    uint32_t sVs = sBase + (uint32_t)(2*KS_SZ)*4;
    uint32_t sPs = sVs + (uint32_t)(2*VS_SZ)*4;

    int tid = threadIdx.x;
    int lane = tid & 31, warp = tid >> 5;
    int g = lane >> 2, tg = lane & 3;
    int lrow = lane & 15, lcol = (lane >> 4) << 2;
    int wq = warp * 16;
    int spv = sp[bi];
    float slope = exp2f(-0.5f * (float)(hi + 1));

    #pragma unroll
    for (int p = 0; p < 8; p++) {
        int i = tid + (p << 8);
        int r = i >> 4, c = (i & 15) << 2;
        *(float4*)&Ps[r*PS_LD + c] = *(const float4*)(Qb + (size_t)(q0 + r)*DD + c);
    }
    __syncthreads();
    uint32_t aq[8][4];
    #pragma unroll
    for (int kf = 0; kf < 8; kf++) {
        uint32_t ad = sPs + (uint32_t)((wq + lrow)*PS_LD + kf*8 + lcol)*4;
        ldsm4(aq[kf], ad);
    }
    __syncthreads();

    int nt = (q0 >= 256) ? (q0 >> 7) + 1 : 8;

    {
        #pragma unroll
        for (int p = 0; p < 8; p++) {
            int i = tid + (p << 8);
            int r = i >> 4, c = (i & 15) << 2;
            cp16(sBase + (uint32_t)(r*KS_LD + c)*4, Kb + (size_t)r*DD + c);
            cp16(sVs   + (uint32_t)(r*VS_LD + c)*4, Vb + (size_t)r*DD + c);
        }
        CP_COMMIT();
    }

    float m_i[2] = {-1e30f, -1e30f};
    float l_i[2] = {0.0f, 0.0f};
    float acc_o[8][4] = {};
    float* Pw = Ps + wq*PS_LD;
    uint32_t sPw = sPs + (uint32_t)(wq*PS_LD)*4;

    for (int t = 0; t < nt; t++) {
        __syncthreads();
        if (t + 1 < nt) {
            int st = (t + 1) & 1;
            const float* Kt = Kb + (size_t)((t+1) << 7)*DD;
            const float* Vt = Vb + (size_t)((t+1) << 7)*DD;
            #pragma unroll
            for (int p = 0; p < 8; p++) {
                int i = tid + (p << 8);
                int r = i >> 4, c = (i & 15) << 2;
                cp16(sBase + (uint32_t)(st*KS_SZ + r*KS_LD + c)*4, Kt + (size_t)r*DD + c);
                cp16(sVs   + (uint32_t)(st*VS_SZ + r*VS_LD + c)*4, Vt + (size_t)r*DD + c);
            }
        }
        CP_COMMIT();
        CP_WAIT1();
        __syncthreads();

        uint32_t ksb = sBase + (uint32_t)((t & 1)*KS_SZ)*4;
        const float* vs = Vs + (t & 1)*VS_SZ;

        float acc_s[16][4] = {};
        #pragma unroll
        for (int kf = 0; kf < 8; kf++) {
            int kc = kf << 3;
            #pragma unroll
            for (int nf2 = 0; nf2 < 8; nf2++) {
                uint32_t kb[4];
                ldsm4(kb, ksb + (uint32_t)((nf2*16 + lrow)*KS_LD + kc + lcol)*4);
                { uint32_t b_[2] = { kb[0], kb[2] }; mma_tf32(acc_s[2*nf2],     aq[kf], b_); }
                { uint32_t b_[2] = { kb[1], kb[3] }; mma_tf32(acc_s[2*nf2 + 1], aq[kf], b_); }
            }
        }

        int c0 = t << 7;
        int qr0 = q0 + wq + g, qr1 = qr0 + 8;
        float tm0 = -1e30f, tm1 = -1e30f;
        #pragma unroll
        for (int nf = 0; nf < 16; nf++) {
            int c = c0 + nf*8 + tg*2;
            #pragma unroll
            for (int j = 0; j < 2; j++) {
                int cc = c + j;
                float s0 = acc_s[nf][j]   * 0.125f + slope * (float)(cc - qr0);
                float s1 = acc_s[nf][j+2] * 0.125f + slope * (float)(cc - qr1);
                bool ok0 = (qr0 >= cc) || (qr0 < spv) || (cc < spv);
                bool ok1 = (qr1 >= cc) || (qr1 < spv) || (cc < spv);
                acc_s[nf][j]   = ok0 ? s0 : -1e9f;
                acc_s[nf][j+2] = ok1 ? s1 : -1e9f;
                tm0 = fmaxf(tm0, acc_s[nf][j]);
                tm1 = fmaxf(tm1, acc_s[nf][j+2]);
            }
        }
        tm0 = fmaxf(tm0, __shfl_xor_sync(0xffffffffu, tm0, 1));
        tm0 = fmaxf(tm0, __shfl_xor_sync(0xffffffffu, tm0, 2));
        tm1 = fmaxf(tm1, __shfl_xor_sync(0xffffffffu, tm1, 1));
        tm1 = fmaxf(tm1, __shfl_xor_sync(0xffffffffu, tm1, 2));

        float mn0 = fmaxf(m_i[0], tm0), mn1 = fmaxf(m_i[1], tm1);
        float al0 = expf(m_i[0] - mn0),  al1 = expf(m_i[1] - mn1);
        m_i[0] = mn0; m_i[1] = mn1;

        float rs0 = 0.0f, rs1 = 0.0f;
        #pragma unroll
        for (int nf = 0; nf < 16; nf++) {
            float p0 = expf(acc_s[nf][0] - mn0);
            float p1 = expf(acc_s[nf][1] - mn0);
            float p2 = expf(acc_s[nf][2] - mn1);
            float p3 = expf(acc_s[nf][3] - mn1);
            rs0 += p0 + p1; rs1 += p2 + p3;
            int col = nf*8 + tg*2;
            *(float2*)&Pw[g*PS_LD + col]     = make_float2(tf32r(p0), tf32r(p1));
            *(float2*)&Pw[(g+8)*PS_LD + col] = make_float2(tf32r(p2), tf32r(p3));
        }
        rs0 += __shfl_xor_sync(0xffffffffu, rs0, 1);
        rs0 += __shfl_xor_sync(0xffffffffu, rs0, 2);
        rs1 += __shfl_xor_sync(0xffffffffu, rs1, 1);
        rs1 += __shfl_xor_sync(0xffffffffu, rs1, 2);
        l_i[0] = l_i[0]*al0 + rs0;
        l_i[1] = l_i[1]*al1 + rs1;

        #pragma unroll
        for (int nf = 0; nf < 8; nf++) {
            acc_o[nf][0] *= al0; acc_o[nf][1] *= al0;
            acc_o[nf][2] *= al1; acc_o[nf][3] *= al1;
        }
        __syncwarp();

        #pragma unroll
        for (int kf = 0; kf < 16; kf++) {
            int kc = kf << 3;
            uint32_t af[4];
            ldsm4(af, sPw + (uint32_t)(lrow*PS_LD + kc + lcol)*4);
            #pragma unroll
            for (int nf = 0; nf < 8; nf++) {
                uint32_t bf[2];
                const float* q2 = vs + (kc + tg)*VS_LD + nf*8 + g;
                bf[0] = __float_as_uint(q2[0]);
                bf[1] = __float_as_uint(q2[4*VS_LD]);
                mma_tf32(acc_o[nf], af, bf);
            }
        }
        __syncwarp();
    }

    float inv0 = 1.0f / l_i[0], inv1 = 1.0f / l_i[1];
    int qr0 = q0 + wq + g;
    #pragma unroll
    for (int nf = 0; nf < 8; nf++) {
        int c = nf*8 + tg*2;
        *(float2*)&Ob[(size_t)qr0*DD + c] =
            make_float2(tf32r(acc_o[nf][0]*inv0), tf32r(acc_o[nf][1]*inv0));
        *(float2*)&Ob[(size_t)(qr0+8)*DD + c] =
            make_float2(tf32r(acc_o[nf][2]*inv1), tf32r(acc_o[nf][3]*inv1));
    }
}

// ---------------- residual add + layernorm; writes fp32 out + tf32 out_t --------
__global__ void __launch_bounds__(256) add_ln(
    const float* __restrict__ X, const float* __restrict__ Rs,
    const float* __restrict__ g, const float* __restrict__ bta,
    float* __restrict__ out, float* __restrict__ out_t)
{
    int r = blockIdx.x, tid = threadIdx.x;
    const float4* x4 = (const float4*)(X + (size_t)r * DD);
    const float4* r4 = (const float4*)(Rs + (size_t)r * DD);
    float4 xv = x4[tid], rv = r4[tid];
    float v0 = xv.x + rv.x, v1 = xv.y + rv.y, v2 = xv.z + rv.z, v3 = xv.w + rv.w;
    float s1 = v0 + v1 + v2 + v3;
    float s2 = v0*v0 + v1*v1 + v2*v2 + v3*v3;

    __shared__ float rA[256], rB[256];
    rA[tid] = s1; rB[tid] = s2; __syncthreads();
    for (int s = 128; s > 0; s >>= 1) {
        if (tid < s) { rA[tid] += rA[tid + s]; rB[tid] += rB[tid + s]; }
        __syncthreads();
    }
    float mu = rA[0] * (1.0f / 1024.0f);
    float var = rB[0] * (1.0f / 1024.0f) - mu * mu;
    float rstd = rsqrtf(var + 1e-5f);

    const float4 gv = ((const float4*)g)[tid];
    const float4 bv = ((const float4*)bta)[tid];
    float4 o;
    o.x = (v0 - mu) * rstd * gv.x + bv.x;
    o.y = (v1 - mu) * rstd * gv.y + bv.y;
    o.z = (v2 - mu) * rstd * gv.z + bv.z;
    o.w = (v3 - mu) * rstd * gv.w + bv.w;
    ((float4*)(out + (size_t)r * DD))[tid] = o;
    float4 t = make_float4(tf32r(o.x), tf32r(o.y), tf32r(o.z), tf32r(o.w));
    ((float4*)(out_t + (size_t)r * DD))[tid] = t;
}

// ---------------- launch ----------------
extern "C" void kernel_launch(void* const* d_in, const int* in_sizes, int n_in,
                              void* d_out, int out_size) {
    (void)in_sizes; (void)n_in; (void)out_size;
    const int*   x    = (const int*)  d_in[0];
    const int*   sp   = (const int*)  d_in[1];
    const float* emb  = (const float*)d_in[2];
    const float* Wq   = (const float*)d_in[3];
    const float* bq   = (const float*)d_in[4];
    const float* Wk   = (const float*)d_in[5];
    const float* bk   = (const float*)d_in[6];
    const float* Wv   = (const float*)d_in[7];
    const float* bv   = (const float*)d_in[8];
    const float* Wo   = (const float*)d_in[9];
    const float* bo   = (const float*)d_in[10];
    const float* ln1g = (const float*)d_in[11];
    const float* ln1b = (const float*)d_in[12];
    const float* W1   = (const float*)d_in[13];
    const float* b1   = (const float*)d_in[14];
    const float* W2   = (const float*)d_in[15];
    const float* b2   = (const float*)d_in[16];
    const float* ln2g = (const float*)d_in[17];
    const float* ln2b = (const float*)d_in[18];
    const float* fcw  = (const float*)d_in[19];
    const float* fcb  = (const float*)d_in[20];
    float* out = (float*)d_out;

    float *h, *ht, *q, *k, *v, *attn, *tmp, *ffn, *wt;
    cudaGetSymbolAddress((void**)&h,    g_h);
    cudaGetSymbolAddress((void**)&ht,   g_ht);
    cudaGetSymbolAddress((void**)&q,    g_q);
    cudaGetSymbolAddress((void**)&k,    g_k);
    cudaGetSymbolAddress((void**)&v,    g_v);
    cudaGetSymbolAddress((void**)&attn, g_attn);
    cudaGetSymbolAddress((void**)&tmp,  g_tmp);
    cudaGetSymbolAddress((void**)&ffn,  g_ffn);
    cudaGetSymbolAddress((void**)&wt,   g_wt);

    static int inited = 0;
    static cudaStream_t side;
    static cudaEvent_t evFork, evQKV[LL], evWOF[LL], evFC;
    if (!inited) {
        cudaFuncSetAttribute(gemm_tc,    cudaFuncAttributeMaxDynamicSharedMemorySize, GEMM_SMEM);
        cudaFuncSetAttribute(flash_attn, cudaFuncAttributeMaxDynamicSharedMemorySize, FA_SMEM);
        cudaStreamCreateWithFlags(&side, cudaStreamNonBlocking);
        cudaEventCreateWithFlags(&evFork, cudaEventDisableTiming);
        for (int l = 0; l < LL; l++) {
            cudaEventCreateWithFlags(&evQKV[l], cudaEventDisableTiming);
            cudaEventCreateWithFlags(&evWOF[l], cudaEventDisableTiming);
        }
        cudaEventCreateWithFlags(&evFC, cudaEventDisableTiming);
        inited = 1;
    }

    const float* NUL = 0;
    float* NULF = 0;

    // ---- side stream: weight transpose + tf32 round prepass, fine-grained events ----
    cudaEventRecord(evFork, 0);
    cudaStreamWaitEvent(side, evFork, 0);
    for (int l = 0; l < LL; l++) {
        size_t lb = (size_t)l * LAYER_WT;
        transpose_round<<<dim3(16, 16), 256, 0, side>>>(Wq + (size_t)l*DD*DD,  wt + lb + OFF_WQ, DD, DD);
        transpose_round<<<dim3(16, 16), 256, 0, side>>>(Wk + (size_t)l*DD*DD,  wt + lb + OFF_WK, DD, DD);
        transpose_round<<<dim3(16, 16), 256, 0, side>>>(Wv + (size_t)l*DD*DD,  wt + lb + OFF_WV, DD, DD);
        cudaEventRecord(evQKV[l], side);
        transpose_round<<<dim3(16, 16), 256, 0, side>>>(Wo + (size_t)l*DD*DD,  wt + lb + OFF_WO, DD, DD);
        transpose_round<<<dim3(16, 64), 256, 0, side>>>(W1 + (size_t)l*DD*DFFN, wt + lb + OFF_W1, DD, DFFN);
        transpose_round<<<dim3(64, 16), 256, 0, side>>>(W2 + (size_t)l*DFFN*DD, wt + lb + OFF_W2, DFFN, DD);
        cudaEventRecord(evWOF[l], side);
    }
    transpose_round<<<dim3(16, 500), 256, 0, side>>>(fcw, wt + OFF_FC, DD, OUTV);
    cudaEventRecord(evFC, side);

    // ---- main stream ----
    embed_kernel<<<MTOK, 256>>>(x, emb, h, ht);

    for (int l = 0; l < LL; l++) {
        size_t lb = (size_t)l * LAYER_WT;

        cudaStreamWaitEvent(0, evQKV[l], 0);
        gemm_tc<<<dim3(MTOK/128, DD/128, 3), 256, GEMM_SMEM>>>(
            ht, DD, DD, 4, (const int*)0,
            wt + lb + OFF_WQ, bq + (size_t)l*DD, q,
            wt + lb + OFF_WK, bk + (size_t)l*DD, k,
            wt + lb + OFF_WV, bv + (size_t)l*DD, v);

        flash_attn<<<dim3(SS/128, 1, BB*HH), 256, FA_SMEM>>>(q, k, v, attn, sp);

        cudaStreamWaitEvent(0, evWOF[l], 0);
        gemm_tc<<<dim3(MTOK/128, DD/128, 1), 256, GEMM_SMEM>>>(
            attn, DD, DD, 0, (const int*)0,
            wt + lb + OFF_WO, bo + (size_t)l*DD, tmp,
            NUL, NUL, NULF, NUL, NUL, NULF);
        add_ln<<<MTOK, 256>>>(h, tmp, ln1g + (size_t)l*DD, ln1b + (size_t)l*DD, h, ht);

        gemm_tc<<<dim3(MTOK/128, DFFN/128, 1), 256, GEMM_SMEM>>>(
            ht, DD, DFFN, 1 | 4, (const int*)0,
            wt + lb + OFF_W1, b1 + (size_t)l*DFFN, ffn,
            NUL, NUL, NULF, NUL, NUL, NULF);
        gemm_tc<<<dim3(MTOK/128, DD/128, 1), 256, GEMM_SMEM>>>(
            ffn, DFFN, DD, 0, (const int*)0,
            wt + lb + OFF_W2, b2 + (size_t)l*DD, tmp,
            NUL, NUL, NULF, NUL, NUL, NULF);
        add_ln<<<MTOK, 256>>>(h, tmp, ln2g + (size_t)l*DD, ln2b + (size_t)l*DD, h, ht);
    }

    cudaStreamWaitEvent(0, evFC, 0);
    gemm_tc<<<dim3(MTOK/128, OUTV/128, 1), 256, GEMM_SMEM>>>(
        ht, DD, OUTV, 2, sp,
        wt + OFF_FC, fcb, out,
        NUL, NUL, NULF, NUL, NUL, NULF);
}